// round 2
// baseline (speedup 1.0000x reference)
#include <cuda_runtime.h>
#include <cuda_bf16.h>
#include <cstddef>

// Scratch (no cudaMalloc allowed): M = V1 + W·x2  (K x D), c = b + V2·x2 (K)
__device__ float g_M[64 * 1024];
__device__ float g_c[64];

// ---------------------------------------------------------------------------
// Kernel A: M[k,d] = V[k,d] + sum_e W[k,d,e] * x2[e]
// One warp per (k,d) pair. 65536 pairs, 8 warps/block -> 8192 blocks.
// HBM-bound: streams 256 MB of W once, coalesced float4, MLP=8 per lane.
// ---------------------------------------------------------------------------
__global__ __launch_bounds__(256) void wx2_kernel(const float* __restrict__ W,
                                                  const float* __restrict__ V,
                                                  const float* __restrict__ x2) {
    __shared__ float sx2[1024];
    // stage x2 (4 KB) into smem once per block
    {
        const float4* src = reinterpret_cast<const float4*>(x2);
        float4* dst = reinterpret_cast<float4*>(sx2);
        dst[threadIdx.x] = src[threadIdx.x];  // 256 threads x float4 = 1024 floats
    }
    __syncthreads();

    int pair = blockIdx.x * 8 + (threadIdx.x >> 5);  // k*1024 + d
    int lane = threadIdx.x & 31;
    int k = pair >> 10;
    int d = pair & 1023;

    const float4* w = reinterpret_cast<const float4*>(W + (size_t)pair * 1024);
    const float4* xx = reinterpret_cast<const float4*>(sx2);

    float s = 0.0f;
#pragma unroll
    for (int i = 0; i < 8; i++) {
        float4 wv = w[lane + i * 32];
        float4 xv = xx[lane + i * 32];
        s += wv.x * xv.x + wv.y * xv.y + wv.z * xv.z + wv.w * xv.w;
    }
#pragma unroll
    for (int o = 16; o; o >>= 1) s += __shfl_xor_sync(0xFFFFFFFFu, s, o);

    if (lane == 0) g_M[pair] = s + V[(size_t)k * 2048 + d];
}

// ---------------------------------------------------------------------------
// Kernel A2: c[k] = b[k] + sum_e V[k, 1024+e] * x2[e]. Tiny: 64 warps.
// ---------------------------------------------------------------------------
__global__ void c_kernel(const float* __restrict__ V,
                         const float* __restrict__ x2,
                         const float* __restrict__ b) {
    int k = blockIdx.x;
    int lane = threadIdx.x;
    const float4* v = reinterpret_cast<const float4*>(V + (size_t)k * 2048 + 1024);
    const float4* xx = reinterpret_cast<const float4*>(x2);
    float s = 0.0f;
#pragma unroll
    for (int i = 0; i < 8; i++) {
        float4 a = v[lane + i * 32];
        float4 c = xx[lane + i * 32];
        s += a.x * c.x + a.y * c.y + a.z * c.z + a.w * c.w;
    }
#pragma unroll
    for (int o = 16; o; o >>= 1) s += __shfl_xor_sync(0xFFFFFFFFu, s, o);
    if (lane == 0) g_c[k] = s + b[k];
}

// ---------------------------------------------------------------------------
// Kernel B: out[n] = sum_k relu( (x1 @ M^T)[n,k] + c[k] ) * U[k]
// Classic smem-tiled fp32 GEMM, BM=64 rows x K=64 cols per block, BK=32.
// 256 threads as 16x16; each thread owns a 4x4 register tile.
// Fused epilogue: relu + scale-by-U + row reduction -> out (N,1).
// Grid = 8192/64 = 128 blocks.
// ---------------------------------------------------------------------------
#define BM 64
#define BK 32

__global__ __launch_bounds__(256) void gemm_kernel(const float* __restrict__ x1,
                                                   const float* __restrict__ U,
                                                   float* __restrict__ out) {
    __shared__ float As[BK][BM + 1];   // [d][row], padded: conflict-free
    __shared__ float Bs[BK][64 + 1];   // [d][k]

    int tid = threadIdx.x;
    int tx = tid & 15;        // k-dim group
    int ty = tid >> 4;        // row-dim group
    int row0 = blockIdx.x * BM;

    float acc[4][4] = {};

    for (int d0 = 0; d0 < 1024; d0 += BK) {
        // load x1 tile: 64 rows x 32 d = 2048 floats, 8/thread, coalesced in d
#pragma unroll
        for (int i = 0; i < 8; i++) {
            int idx = tid + i * 256;
            int r = idx >> 5;
            int d = idx & 31;
            As[d][r] = x1[(size_t)(row0 + r) * 1024 + d0 + d];
        }
        // load M tile: 64 k x 32 d = 2048 floats
#pragma unroll
        for (int i = 0; i < 8; i++) {
            int idx = tid + i * 256;
            int kk = idx >> 5;
            int d = idx & 31;
            Bs[d][kk] = g_M[(size_t)kk * 1024 + d0 + d];
        }
        __syncthreads();

#pragma unroll
        for (int dd = 0; dd < BK; dd++) {
            float a[4], bv[4];
#pragma unroll
            for (int i = 0; i < 4; i++) a[i] = As[dd][ty + i * 16];
#pragma unroll
            for (int j = 0; j < 4; j++) bv[j] = Bs[dd][tx + j * 16];
#pragma unroll
            for (int i = 0; i < 4; i++)
#pragma unroll
                for (int j = 0; j < 4; j++) acc[i][j] += a[i] * bv[j];
        }
        __syncthreads();
    }

    // Fused epilogue: relu(acc + c[k]) * U[k], reduce over k per row.
    __shared__ float red[BM][17];
#pragma unroll
    for (int i = 0; i < 4; i++) {
        float p = 0.0f;
#pragma unroll
        for (int j = 0; j < 4; j++) {
            int k = tx + j * 16;
            float f = acc[i][j] + g_c[k];
            f = f > 0.0f ? f : 0.0f;
            p += f * U[k];
        }
        red[ty + i * 16][tx] = p;
    }
    __syncthreads();
    if (tid < BM) {
        float s = 0.0f;
#pragma unroll
        for (int t = 0; t < 16; t++) s += red[tid][t];
        out[row0 + tid] = s;
    }
}

// ---------------------------------------------------------------------------
extern "C" void kernel_launch(void* const* d_in, const int* in_sizes, int n_in,
                              void* d_out, int out_size) {
    const float* x1 = (const float*)d_in[0];  // (8192, 1024)
    const float* x2 = (const float*)d_in[1];  // (1, 1024)
    const float* V  = (const float*)d_in[2];  // (64, 2048)
    const float* W  = (const float*)d_in[3];  // (64, 1024, 1024)
    const float* b  = (const float*)d_in[4];  // (64,)
    const float* U  = (const float*)d_in[5];  // (64, 1)
    float* out = (float*)d_out;               // (8192, 1)

    wx2_kernel<<<8192, 256>>>(W, V, x2);   // HBM-bound: 256 MB of W
    c_kernel<<<64, 32>>>(V, x2, b);        // tiny
    gemm_kernel<<<128, 256>>>(x1, U, out); // FFMA-bound GEMM + fused epilogue
}

// round 4
// speedup vs baseline: 2.5327x; 2.5327x over previous
#include <cuda_runtime.h>
#include <cuda_bf16.h>
#include <cstdint>
#include <cstddef>

// ---------------------------------------------------------------------------
// Scratch (__device__ globals; no cudaMalloc allowed)
// ---------------------------------------------------------------------------
__device__ float g_c[64];
__device__ __align__(16) __nv_bfloat16 g_Mhi[64 * 1024];
__device__ __align__(16) __nv_bfloat16 g_Mlo[64 * 1024];

// ---------------------------------------------------------------------------
// Kernel A: M[k,d] = V[k,d] + sum_e W[k,d,e]*x2[e]  -> split to bf16 hi/lo.
// One warp per (k,d). Streams 256 MB of W once; HBM-bound (~80% DRAM).
// ---------------------------------------------------------------------------
__global__ __launch_bounds__(256) void wx2_kernel(const float* __restrict__ W,
                                                  const float* __restrict__ V,
                                                  const float* __restrict__ x2) {
    __shared__ float sx2[1024];
    {
        const float4* src = reinterpret_cast<const float4*>(x2);
        float4* dst = reinterpret_cast<float4*>(sx2);
        dst[threadIdx.x] = src[threadIdx.x];
    }
    __syncthreads();

    int pair = blockIdx.x * 8 + (threadIdx.x >> 5);
    int lane = threadIdx.x & 31;
    int k = pair >> 10;
    int d = pair & 1023;

    const float4* w = reinterpret_cast<const float4*>(W + (size_t)pair * 1024);
    const float4* xx = reinterpret_cast<const float4*>(sx2);

    float s = 0.0f;
#pragma unroll
    for (int i = 0; i < 8; i++) {
        float4 wv = w[lane + i * 32];
        float4 xv = xx[lane + i * 32];
        s += wv.x * xv.x + wv.y * xv.y + wv.z * xv.z + wv.w * xv.w;
    }
#pragma unroll
    for (int o = 16; o; o >>= 1) s += __shfl_xor_sync(0xFFFFFFFFu, s, o);

    if (lane == 0) {
        float m = s + V[(size_t)k * 2048 + d];
        __nv_bfloat16 hi = __float2bfloat16_rn(m);
        __nv_bfloat16 lo = __float2bfloat16_rn(m - __bfloat162float(hi));
        g_Mhi[pair] = hi;
        g_Mlo[pair] = lo;
    }
}

// ---------------------------------------------------------------------------
// Kernel A2: c[k] = b[k] + sum_e V[k,1024+e]*x2[e]
// ---------------------------------------------------------------------------
__global__ void c_kernel(const float* __restrict__ V,
                         const float* __restrict__ x2,
                         const float* __restrict__ b) {
    int k = blockIdx.x;
    int lane = threadIdx.x;
    const float4* v = reinterpret_cast<const float4*>(V + (size_t)k * 2048 + 1024);
    const float4* xx = reinterpret_cast<const float4*>(x2);
    float s = 0.0f;
#pragma unroll
    for (int i = 0; i < 8; i++) {
        float4 a = v[lane + i * 32];
        float4 c = xx[lane + i * 32];
        s += a.x * c.x + a.y * c.y + a.z * c.z + a.w * c.w;
    }
#pragma unroll
    for (int o = 16; o; o >>= 1) s += __shfl_xor_sync(0xFFFFFFFFu, s, o);
    if (lane == 0) g_c[k] = s + b[k];
}

// ---------------------------------------------------------------------------
// Kernel B: mma.sync split-bf16 GEMM + fused relu/U epilogue.
// out[n] = sum_k relu((x1 @ M^T)[n,k] + c[k]) * U[k]
// CTA: 256 thr (8 warps), BM=64 rows x 64 cols, D in 16 chunks of 64.
// Warp (wr=wid&3, wc=wid>>2): rows wr*16..+15, cols wc*32..+31 (4 n-tiles).
// Double-buffered smem; ld=72 bf16 so fragment LDS are conflict-free.
// ---------------------------------------------------------------------------
#define LDA       72
#define AHI_OFF   0
#define ALO_OFF   9216
#define BHI_OFF   18432
#define BLO_OFF   27648
#define STAGE_BYTES 36864
#define C_OFF     (2 * STAGE_BYTES)      // 73728
#define U_OFF     (C_OFF + 256)
#define RED_OFF   (U_OFF + 256)
#define SMEM_TOTAL (RED_OFF + 512)

__device__ __forceinline__ uint32_t pack_bf16x2(__nv_bfloat16 a, __nv_bfloat16 b) {
    __nv_bfloat162 t; t.x = a; t.y = b;
    return *reinterpret_cast<uint32_t*>(&t);
}

__device__ __forceinline__ void split_pair(float f0, float f1, uint32_t& h, uint32_t& l) {
    __nv_bfloat16 h0 = __float2bfloat16_rn(f0);
    __nv_bfloat16 h1 = __float2bfloat16_rn(f1);
    h = pack_bf16x2(h0, h1);
    l = pack_bf16x2(__float2bfloat16_rn(f0 - __bfloat162float(h0)),
                    __float2bfloat16_rn(f1 - __bfloat162float(h1)));
}

__device__ __forceinline__ void mma16816(float d[4], const uint32_t a[4],
                                         uint32_t b0, uint32_t b1) {
    asm volatile(
        "mma.sync.aligned.m16n8k16.row.col.f32.bf16.bf16.f32 "
        "{%0,%1,%2,%3}, {%4,%5,%6,%7}, {%8,%9}, {%0,%1,%2,%3};"
        : "+f"(d[0]), "+f"(d[1]), "+f"(d[2]), "+f"(d[3])
        : "r"(a[0]), "r"(a[1]), "r"(a[2]), "r"(a[3]), "r"(b0), "r"(b1));
}

__device__ __forceinline__ void ldg_chunk(const float* __restrict__ x1, int row0, int ch,
                                          int tid, float4 pa[4], uint4 pbh[2], uint4 pbl[2]) {
#pragma unroll
    for (int t = 0; t < 4; t++) {
        int g = tid + t * 256;              // 0..1023
        int r = g >> 4;                     // row 0..63
        int c4 = (g & 15) * 4;              // col 0..60
        pa[t] = *reinterpret_cast<const float4*>(x1 + (size_t)(row0 + r) * 1024 + ch * 64 + c4);
    }
#pragma unroll
    for (int t = 0; t < 2; t++) {
        int g = tid + t * 256;              // 0..511
        int n = g >> 3;                     // k_out 0..63
        int k8 = (g & 7) * 8;               // col 0..56
        pbh[t] = *reinterpret_cast<const uint4*>(g_Mhi + (size_t)n * 1024 + ch * 64 + k8);
        pbl[t] = *reinterpret_cast<const uint4*>(g_Mlo + (size_t)n * 1024 + ch * 64 + k8);
    }
}

__device__ __forceinline__ void sts_chunk(char* stage, int tid, const float4 pa[4],
                                          const uint4 pbh[2], const uint4 pbl[2]) {
#pragma unroll
    for (int t = 0; t < 4; t++) {
        int g = tid + t * 256;
        int r = g >> 4;
        int c4 = (g & 15) * 4;
        uint32_t h0, l0, h1, l1;
        split_pair(pa[t].x, pa[t].y, h0, l0);
        split_pair(pa[t].z, pa[t].w, h1, l1);
        int off = (r * LDA + c4) * 2;
        *reinterpret_cast<uint2*>(stage + AHI_OFF + off) = make_uint2(h0, h1);
        *reinterpret_cast<uint2*>(stage + ALO_OFF + off) = make_uint2(l0, l1);
    }
#pragma unroll
    for (int t = 0; t < 2; t++) {
        int g = tid + t * 256;
        int n = g >> 3;
        int k8 = (g & 7) * 8;
        int off = (n * LDA + k8) * 2;       // 16B aligned (144 | 16)
        *reinterpret_cast<uint4*>(stage + BHI_OFF + off) = pbh[t];
        *reinterpret_cast<uint4*>(stage + BLO_OFF + off) = pbl[t];
    }
}

__device__ __forceinline__ void compute_chunk(const char* stage, int m0, int nb,
                                              int lane, float d[4][4]) {
    const __nv_bfloat16* Ah = reinterpret_cast<const __nv_bfloat16*>(stage + AHI_OFF);
    const __nv_bfloat16* Al = reinterpret_cast<const __nv_bfloat16*>(stage + ALO_OFF);
    const __nv_bfloat16* Bh = reinterpret_cast<const __nv_bfloat16*>(stage + BHI_OFF);
    const __nv_bfloat16* Bl = reinterpret_cast<const __nv_bfloat16*>(stage + BLO_OFF);
    int g = lane >> 2, tg2 = (lane & 3) * 2;
#pragma unroll
    for (int ks = 0; ks < 4; ks++) {
        int k0 = ks * 16;
        int abase = (m0 + g) * LDA + k0 + tg2;
        uint32_t ah[4], al[4];
        ah[0] = *reinterpret_cast<const uint32_t*>(Ah + abase);
        ah[1] = *reinterpret_cast<const uint32_t*>(Ah + abase + 8 * LDA);
        ah[2] = *reinterpret_cast<const uint32_t*>(Ah + abase + 8);
        ah[3] = *reinterpret_cast<const uint32_t*>(Ah + abase + 8 * LDA + 8);
        al[0] = *reinterpret_cast<const uint32_t*>(Al + abase);
        al[1] = *reinterpret_cast<const uint32_t*>(Al + abase + 8 * LDA);
        al[2] = *reinterpret_cast<const uint32_t*>(Al + abase + 8);
        al[3] = *reinterpret_cast<const uint32_t*>(Al + abase + 8 * LDA + 8);
#pragma unroll
        for (int j = 0; j < 4; j++) {
            int bbase = (nb + j * 8 + g) * LDA + k0 + tg2;
            uint32_t bh0 = *reinterpret_cast<const uint32_t*>(Bh + bbase);
            uint32_t bh1 = *reinterpret_cast<const uint32_t*>(Bh + bbase + 8);
            uint32_t bl0 = *reinterpret_cast<const uint32_t*>(Bl + bbase);
            uint32_t bl1 = *reinterpret_cast<const uint32_t*>(Bl + bbase + 8);
            mma16816(d[j], ah, bh0, bh1);
            mma16816(d[j], ah, bl0, bl1);
            mma16816(d[j], al, bh0, bh1);
        }
    }
}

__global__ __launch_bounds__(256, 1) void gemm_mma(const float* __restrict__ x1,
                                                   const float* __restrict__ U,
                                                   float* __restrict__ out) {
    extern __shared__ char smem[];
    int tid = threadIdx.x, lane = tid & 31, wid = tid >> 5;
    int wr = wid & 3, wc = wid >> 2;
    int m0 = wr * 16, nb = wc * 32;
    int row0 = blockIdx.x * 64;

    float* sc = reinterpret_cast<float*>(smem + C_OFF);
    float* su = reinterpret_cast<float*>(smem + U_OFF);
    float* red = reinterpret_cast<float*>(smem + RED_OFF);
    if (tid < 64) {
        sc[tid] = g_c[tid];
        su[tid] = U[tid];
    }

    float d[4][4] = {};
    float4 pa[4];
    uint4 pbh[2], pbl[2];

    ldg_chunk(x1, row0, 0, tid, pa, pbh, pbl);
    sts_chunk(smem, tid, pa, pbh, pbl);
    __syncthreads();

    for (int ch = 0; ch < 16; ch++) {
        if (ch < 15) ldg_chunk(x1, row0, ch + 1, tid, pa, pbh, pbl);
        compute_chunk(smem + (ch & 1) * STAGE_BYTES, m0, nb, lane, d);
        if (ch < 15) {
            sts_chunk(smem + ((ch + 1) & 1) * STAGE_BYTES, tid, pa, pbh, pbl);
            __syncthreads();
        }
    }

    // fused epilogue: relu(D + c)*U, row-reduce over 64 cols -> out (N,1)
    int g = lane >> 2, tg2 = (lane & 3) * 2;
    float accA = 0.0f, accB = 0.0f;
#pragma unroll
    for (int j = 0; j < 4; j++) {
        int col = nb + j * 8 + tg2;
        float c0 = sc[col], c1 = sc[col + 1];
        float u0 = su[col], u1 = su[col + 1];
        accA += fmaxf(d[j][0] + c0, 0.0f) * u0 + fmaxf(d[j][1] + c1, 0.0f) * u1;
        accB += fmaxf(d[j][2] + c0, 0.0f) * u0 + fmaxf(d[j][3] + c1, 0.0f) * u1;
    }
    accA += __shfl_xor_sync(0xFFFFFFFFu, accA, 1);
    accA += __shfl_xor_sync(0xFFFFFFFFu, accA, 2);
    accB += __shfl_xor_sync(0xFFFFFFFFu, accB, 1);
    accB += __shfl_xor_sync(0xFFFFFFFFu, accB, 2);
    if ((lane & 3) == 0) {
        red[wc * 64 + m0 + g] = accA;
        red[wc * 64 + m0 + 8 + g] = accB;
    }
    __syncthreads();
    if (tid < 64) out[row0 + tid] = red[tid] + red[64 + tid];
}

// ---------------------------------------------------------------------------
extern "C" void kernel_launch(void* const* d_in, const int* in_sizes, int n_in,
                              void* d_out, int out_size) {
    const float* x1 = (const float*)d_in[0];  // (8192, 1024)
    const float* x2 = (const float*)d_in[1];  // (1, 1024)
    const float* V  = (const float*)d_in[2];  // (64, 2048)
    const float* W  = (const float*)d_in[3];  // (64, 1024, 1024)
    const float* b  = (const float*)d_in[4];  // (64,)
    const float* U  = (const float*)d_in[5];  // (64, 1)
    float* out = (float*)d_out;               // (8192, 1)

    cudaFuncSetAttribute(gemm_mma, cudaFuncAttributeMaxDynamicSharedMemorySize, SMEM_TOTAL);

    wx2_kernel<<<8192, 256>>>(W, V, x2);             // HBM-bound: 256 MB of W
    c_kernel<<<64, 32>>>(V, x2, b);                  // tiny
    gemm_mma<<<128, 256, SMEM_TOTAL>>>(x1, U, out);  // HMMA split-bf16 GEMM + epilogue
}

// round 5
// speedup vs baseline: 2.8342x; 1.1190x over previous
#include <cuda_runtime.h>
#include <cuda_bf16.h>
#include <cstdint>
#include <cstddef>

// ---------------------------------------------------------------------------
// Scratch (__device__ globals; no cudaMalloc allowed)
// ---------------------------------------------------------------------------
__device__ float g_c[64];
__device__ __align__(16) __nv_bfloat16 g_Mhi[64 * 1024];
__device__ __align__(16) __nv_bfloat16 g_Mlo[64 * 1024];

// ---------------------------------------------------------------------------
// Kernel A (fused): blocks [0,8192): M[k,d] = V[k,d] + sum_e W[k,d,e]*x2[e]
//                   blocks [8192,8256): c[k] = b[k] + V2[k]·x2
// One warp per (k,d) pair; streams 256 MB of W once (HBM-bound, ~82% DRAM).
// ---------------------------------------------------------------------------
__global__ __launch_bounds__(256) void wx2_kernel(const float* __restrict__ W,
                                                  const float* __restrict__ V,
                                                  const float* __restrict__ x2,
                                                  const float* __restrict__ b) {
    if (blockIdx.x >= 8192) {
        // ---- c blocks: one per k, warp 0 only
        int k = blockIdx.x - 8192;
        if (threadIdx.x < 32) {
            int lane = threadIdx.x;
            const float4* v = reinterpret_cast<const float4*>(V + (size_t)k * 2048 + 1024);
            const float4* xx = reinterpret_cast<const float4*>(x2);
            float s = 0.0f;
#pragma unroll
            for (int i = 0; i < 8; i++) {
                float4 a = v[lane + i * 32];
                float4 c = xx[lane + i * 32];
                s += a.x * c.x + a.y * c.y + a.z * c.z + a.w * c.w;
            }
#pragma unroll
            for (int o = 16; o; o >>= 1) s += __shfl_xor_sync(0xFFFFFFFFu, s, o);
            if (lane == 0) g_c[k] = s + b[k];
        }
        return;
    }

    __shared__ float sx2[1024];
    {
        const float4* src = reinterpret_cast<const float4*>(x2);
        float4* dst = reinterpret_cast<float4*>(sx2);
        dst[threadIdx.x] = src[threadIdx.x];
    }
    __syncthreads();

    int pair = blockIdx.x * 8 + (threadIdx.x >> 5);
    int lane = threadIdx.x & 31;
    int k = pair >> 10;
    int d = pair & 1023;

    const float4* w = reinterpret_cast<const float4*>(W + (size_t)pair * 1024);
    const float4* xx = reinterpret_cast<const float4*>(sx2);

    float s = 0.0f;
#pragma unroll
    for (int i = 0; i < 8; i++) {
        float4 wv = __ldcs(&w[lane + i * 32]);   // streaming: W touched exactly once
        float4 xv = xx[lane + i * 32];
        s += wv.x * xv.x + wv.y * xv.y + wv.z * xv.z + wv.w * xv.w;
    }
#pragma unroll
    for (int o = 16; o; o >>= 1) s += __shfl_xor_sync(0xFFFFFFFFu, s, o);

    if (lane == 0) {
        float m = s + V[(size_t)k * 2048 + d];
        __nv_bfloat16 hi = __float2bfloat16_rn(m);
        __nv_bfloat16 lo = __float2bfloat16_rn(m - __bfloat162float(hi));
        g_Mhi[pair] = hi;
        g_Mlo[pair] = lo;
    }
}

// ---------------------------------------------------------------------------
// Kernel B: mma.sync split-bf16 GEMM + fused relu/U epilogue.
// out[n] = sum_k relu((x1 @ M^T)[n,k] + c[k]) * U[k]
// CTA: 256 thr (8 warps), BM=64 rows x 64 cols, D in 8 chunks of 128.
// Warp (wr=wid&3, wc=wid>>2): rows wr*16..+15, cols wc*32..+31.
// Double-buffered smem (2 x 68KB); LDA=136 bf16 -> conflict-free LDS/STS.
// ---------------------------------------------------------------------------
#define CHUNK     128
#define LDA       136
#define AHI_OFF   0
#define ALO_OFF   17408
#define BHI_OFF   34816
#define BLO_OFF   52224
#define STAGE_BYTES 69632
#define C_OFF     (2 * STAGE_BYTES)      // 139264
#define U_OFF     (C_OFF + 256)
#define RED_OFF   (U_OFF + 256)
#define SMEM_TOTAL (RED_OFF + 512)

__device__ __forceinline__ uint32_t pack_bf16x2(__nv_bfloat16 a, __nv_bfloat16 b) {
    __nv_bfloat162 t; t.x = a; t.y = b;
    return *reinterpret_cast<uint32_t*>(&t);
}

__device__ __forceinline__ void split_pair(float f0, float f1, uint32_t& h, uint32_t& l) {
    __nv_bfloat16 h0 = __float2bfloat16_rn(f0);
    __nv_bfloat16 h1 = __float2bfloat16_rn(f1);
    h = pack_bf16x2(h0, h1);
    l = pack_bf16x2(__float2bfloat16_rn(f0 - __bfloat162float(h0)),
                    __float2bfloat16_rn(f1 - __bfloat162float(h1)));
}

__device__ __forceinline__ void mma16816(float d[4], const uint32_t a[4],
                                         uint32_t b0, uint32_t b1) {
    asm volatile(
        "mma.sync.aligned.m16n8k16.row.col.f32.bf16.bf16.f32 "
        "{%0,%1,%2,%3}, {%4,%5,%6,%7}, {%8,%9}, {%0,%1,%2,%3};"
        : "+f"(d[0]), "+f"(d[1]), "+f"(d[2]), "+f"(d[3])
        : "r"(a[0]), "r"(a[1]), "r"(a[2]), "r"(a[3]), "r"(b0), "r"(b1));
}

// LDG one 128-wide chunk into registers (16 x LDG.128 per thread, batched MLP)
__device__ __forceinline__ void ldg_chunk(const float* __restrict__ x1, int row0, int ch,
                                          int tid, float4 pa[8], uint4 pbh[4], uint4 pbl[4]) {
#pragma unroll
    for (int t = 0; t < 8; t++) {
        int g = tid + t * 256;              // 0..2047
        int r = g >> 5;                     // row 0..63
        int c4 = (g & 31) * 4;              // col 0..124
        pa[t] = *reinterpret_cast<const float4*>(x1 + (size_t)(row0 + r) * 1024 + ch * CHUNK + c4);
    }
#pragma unroll
    for (int t = 0; t < 4; t++) {
        int g = tid + t * 256;              // 0..1023
        int n = g >> 4;                     // k_out 0..63
        int k8 = (g & 15) * 8;              // col 0..120
        pbh[t] = *reinterpret_cast<const uint4*>(g_Mhi + (size_t)n * 1024 + ch * CHUNK + k8);
        pbl[t] = *reinterpret_cast<const uint4*>(g_Mlo + (size_t)n * 1024 + ch * CHUNK + k8);
    }
}

__device__ __forceinline__ void sts_chunk(char* stage, int tid, const float4 pa[8],
                                          const uint4 pbh[4], const uint4 pbl[4]) {
#pragma unroll
    for (int t = 0; t < 8; t++) {
        int g = tid + t * 256;
        int r = g >> 5;
        int c4 = (g & 31) * 4;
        uint32_t h0, l0, h1, l1;
        split_pair(pa[t].x, pa[t].y, h0, l0);
        split_pair(pa[t].z, pa[t].w, h1, l1);
        int off = (r * LDA + c4) * 2;
        *reinterpret_cast<uint2*>(stage + AHI_OFF + off) = make_uint2(h0, h1);
        *reinterpret_cast<uint2*>(stage + ALO_OFF + off) = make_uint2(l0, l1);
    }
#pragma unroll
    for (int t = 0; t < 4; t++) {
        int g = tid + t * 256;
        int n = g >> 4;
        int k8 = (g & 15) * 8;
        int off = (n * LDA + k8) * 2;       // 16B aligned
        *reinterpret_cast<uint4*>(stage + BHI_OFF + off) = pbh[t];
        *reinterpret_cast<uint4*>(stage + BLO_OFF + off) = pbl[t];
    }
}

__device__ __forceinline__ void compute_chunk(const char* stage, int m0, int nb,
                                              int lane, float d[4][4]) {
    const __nv_bfloat16* Ah = reinterpret_cast<const __nv_bfloat16*>(stage + AHI_OFF);
    const __nv_bfloat16* Al = reinterpret_cast<const __nv_bfloat16*>(stage + ALO_OFF);
    const __nv_bfloat16* Bh = reinterpret_cast<const __nv_bfloat16*>(stage + BHI_OFF);
    const __nv_bfloat16* Bl = reinterpret_cast<const __nv_bfloat16*>(stage + BLO_OFF);
    int g = lane >> 2, tg2 = (lane & 3) * 2;
#pragma unroll
    for (int ks = 0; ks < CHUNK / 16; ks++) {
        int k0 = ks * 16;
        int abase = (m0 + g) * LDA + k0 + tg2;
        uint32_t ah[4], al[4];
        ah[0] = *reinterpret_cast<const uint32_t*>(Ah + abase);
        ah[1] = *reinterpret_cast<const uint32_t*>(Ah + abase + 8 * LDA);
        ah[2] = *reinterpret_cast<const uint32_t*>(Ah + abase + 8);
        ah[3] = *reinterpret_cast<const uint32_t*>(Ah + abase + 8 * LDA + 8);
        al[0] = *reinterpret_cast<const uint32_t*>(Al + abase);
        al[1] = *reinterpret_cast<const uint32_t*>(Al + abase + 8 * LDA);
        al[2] = *reinterpret_cast<const uint32_t*>(Al + abase + 8);
        al[3] = *reinterpret_cast<const uint32_t*>(Al + abase + 8 * LDA + 8);
#pragma unroll
        for (int j = 0; j < 4; j++) {
            int bbase = (nb + j * 8 + g) * LDA + k0 + tg2;
            uint32_t bh0 = *reinterpret_cast<const uint32_t*>(Bh + bbase);
            uint32_t bh1 = *reinterpret_cast<const uint32_t*>(Bh + bbase + 8);
            uint32_t bl0 = *reinterpret_cast<const uint32_t*>(Bl + bbase);
            uint32_t bl1 = *reinterpret_cast<const uint32_t*>(Bl + bbase + 8);
            mma16816(d[j], ah, bh0, bh1);
            mma16816(d[j], ah, bl0, bl1);
            mma16816(d[j], al, bh0, bh1);
        }
    }
}

__global__ __launch_bounds__(256, 1) void gemm_mma(const float* __restrict__ x1,
                                                   const float* __restrict__ U,
                                                   float* __restrict__ out) {
    extern __shared__ char smem[];
    int tid = threadIdx.x, lane = tid & 31, wid = tid >> 5;
    int wr = wid & 3, wc = wid >> 2;
    int m0 = wr * 16, nb = wc * 32;
    int row0 = blockIdx.x * 64;

    float* sc = reinterpret_cast<float*>(smem + C_OFF);
    float* su = reinterpret_cast<float*>(smem + U_OFF);
    float* red = reinterpret_cast<float*>(smem + RED_OFF);
    if (tid < 64) {
        sc[tid] = g_c[tid];
        su[tid] = U[tid];
    }

    float d[4][4] = {};
    float4 pa[8];
    uint4 pbh[4], pbl[4];

    ldg_chunk(x1, row0, 0, tid, pa, pbh, pbl);
    sts_chunk(smem, tid, pa, pbh, pbl);
    __syncthreads();

    for (int ch = 0; ch < 8; ch++) {
        if (ch < 7) ldg_chunk(x1, row0, ch + 1, tid, pa, pbh, pbl);
        compute_chunk(smem + (ch & 1) * STAGE_BYTES, m0, nb, lane, d);
        if (ch < 7) {
            sts_chunk(smem + ((ch + 1) & 1) * STAGE_BYTES, tid, pa, pbh, pbl);
            __syncthreads();
        }
    }

    // fused epilogue: relu(D + c)*U, row-reduce over 64 cols -> out (N,1)
    int g = lane >> 2, tg2 = (lane & 3) * 2;
    float accA = 0.0f, accB = 0.0f;
#pragma unroll
    for (int j = 0; j < 4; j++) {
        int col = nb + j * 8 + tg2;
        float c0 = sc[col], c1 = sc[col + 1];
        float u0 = su[col], u1 = su[col + 1];
        accA += fmaxf(d[j][0] + c0, 0.0f) * u0 + fmaxf(d[j][1] + c1, 0.0f) * u1;
        accB += fmaxf(d[j][2] + c0, 0.0f) * u0 + fmaxf(d[j][3] + c1, 0.0f) * u1;
    }
    accA += __shfl_xor_sync(0xFFFFFFFFu, accA, 1);
    accA += __shfl_xor_sync(0xFFFFFFFFu, accA, 2);
    accB += __shfl_xor_sync(0xFFFFFFFFu, accB, 1);
    accB += __shfl_xor_sync(0xFFFFFFFFu, accB, 2);
    if ((lane & 3) == 0) {
        red[wc * 64 + m0 + g] = accA;
        red[wc * 64 + m0 + 8 + g] = accB;
    }
    __syncthreads();
    if (tid < 64) out[row0 + tid] = red[tid] + red[64 + tid];
}

// ---------------------------------------------------------------------------
extern "C" void kernel_launch(void* const* d_in, const int* in_sizes, int n_in,
                              void* d_out, int out_size) {
    const float* x1 = (const float*)d_in[0];  // (8192, 1024)
    const float* x2 = (const float*)d_in[1];  // (1, 1024)
    const float* V  = (const float*)d_in[2];  // (64, 2048)
    const float* W  = (const float*)d_in[3];  // (64, 1024, 1024)
    const float* b  = (const float*)d_in[4];  // (64,)
    const float* U  = (const float*)d_in[5];  // (64, 1)
    float* out = (float*)d_out;               // (8192, 1)

    cudaFuncSetAttribute(gemm_mma, cudaFuncAttributeMaxDynamicSharedMemorySize, SMEM_TOTAL);

    wx2_kernel<<<8192 + 64, 256>>>(W, V, x2, b);     // HBM-bound + fused c blocks
    gemm_mma<<<128, 256, SMEM_TOTAL>>>(x1, U, out);  // HMMA split-bf16 GEMM + epilogue
}